// round 2
// baseline (speedup 1.0000x reference)
#include <cuda_runtime.h>

typedef unsigned long long U64;

// ---- packed f32x2 helpers (Blackwell FFMA2 path, PTX-only) ----
__device__ __forceinline__ U64 pk2(float x, float y) {
    U64 r; asm("mov.b64 %0, {%1, %2};" : "=l"(r) : "f"(x), "f"(y)); return r;
}
__device__ __forceinline__ float lo2(U64 v) {
    float x; asm("{ .reg .f32 hi; mov.b64 {%0, hi}, %1; }" : "=f"(x) : "l"(v)); return x;
}
__device__ __forceinline__ float hi2(U64 v) {
    float y; asm("{ .reg .f32 lo; mov.b64 {lo, %0}, %1; }" : "=f"(y) : "l"(v)); return y;
}
__device__ __forceinline__ U64 fma2(U64 a, U64 b, U64 c) {
    U64 d; asm("fma.rn.f32x2 %0, %1, %2, %3;" : "=l"(d) : "l"(a), "l"(b), "l"(c)); return d;
}

// ---- fast transcendentals (ex2/rcp/rsqrt approx: ~1 ulp, safe for 1e-3) ----
__device__ __forceinline__ float ex2f(float x) { float r; asm("ex2.approx.f32 %0, %1;" : "=f"(r) : "f"(x)); return r; }
__device__ __forceinline__ float rcpf(float x) { float r; asm("rcp.approx.f32 %0, %1;" : "=f"(r) : "f"(x)); return r; }
__device__ __forceinline__ float rsqf(float x) { float r; asm("rsqrt.approx.f32 %0, %1;" : "=f"(r) : "f"(x)); return r; }

__device__ __forceinline__ float sigm(float v) {
    // 1/(1+exp(-v)) = 1/(1+2^(-v*log2e))
    return rcpf(1.0f + ex2f(v * -1.4426950408889634f));
}
__device__ __forceinline__ float tanhx(float v) {
    // tanh(v) = 1 - 2/(2^(2v*log2e)+1)
    return fmaf(-2.0f, rcpf(1.0f + ex2f(v * 2.8853900817779268f)), 1.0f);
}

static constexpr int Tn = 1000;
static constexpr int In = 13;
static constexpr int Hn = 13;
static constexpr int Bn = 2048;
static constexpr long long OUT_ELEMS = (long long)Bn * Tn * 2 * Hn;   // 53,248,000
static constexpr long long HN_ELEMS  = 2LL * Bn * Hn;                 // 53,248

// One warp per batch row. Lanes 0-15: forward dir, lanes 16-31: backward dir.
// Within a 16-lane half, lane k (k<13) owns hidden element k: gate rows
// {k, 13+k, 26+k, 39+k} of W_ih and W_hh kept in registers as f32x2 pairs
// (i,f) and (g,o). Per step: layernorm via 16-wide xor reduction, then
// 13 broadcast+FFMA2 iterations per matrix, activations, local c/h update.
__global__ void __launch_bounds__(64, 7) bilstm_kernel(
    const float* __restrict__ x,
    const float* __restrict__ ln_w, const float* __restrict__ ln_b,
    const float* __restrict__ wih_f, const float* __restrict__ whh_f,
    const float* __restrict__ bih_f, const float* __restrict__ bhh_f,
    const float* __restrict__ wih_b, const float* __restrict__ whh_b,
    const float* __restrict__ bih_b, const float* __restrict__ bhh_b,
    float* __restrict__ out)
{
    const int lane = threadIdx.x & 31;
    const int warp = blockIdx.x * (blockDim.x >> 5) + (threadIdx.x >> 5);
    const int b    = warp;                 // 0..2047 (grid sized exactly)
    const int dir  = lane >> 4;            // 0 fwd, 1 bwd
    const int k    = lane & 15;
    const bool active = (k < Hn);
    const int kk   = active ? k : 0;       // safe index for idle lanes 13-15

    const float* Wih = dir ? wih_b : wih_f;
    const float* Whh = dir ? whh_b : whh_f;
    const float* Bih = dir ? bih_b : bih_f;
    const float* Bhh = dir ? bhh_b : bhh_f;

    const int r0 = kk, r1 = Hn + kk, r2 = 2 * Hn + kk, r3 = 3 * Hn + kk;

    // Weights in registers (104 floats = 52 f32x2)
    U64 w_ih_if[In], w_ih_go[In], w_hh_if[In], w_hh_go[In];
#pragma unroll
    for (int j = 0; j < In; ++j) {
        w_ih_if[j] = pk2(Wih[r0 * In + j], Wih[r1 * In + j]);
        w_ih_go[j] = pk2(Wih[r2 * In + j], Wih[r3 * In + j]);
        w_hh_if[j] = pk2(Whh[r0 * Hn + j], Whh[r1 * Hn + j]);
        w_hh_go[j] = pk2(Whh[r2 * Hn + j], Whh[r3 * Hn + j]);
    }
    const U64 bias_if = pk2(Bih[r0] + Bhh[r0], Bih[r1] + Bhh[r1]);
    const U64 bias_go = pk2(Bih[r2] + Bhh[r2], Bih[r3] + Bhh[r3]);
    const float lnw = ln_w[kk];
    const float lnb = ln_b[kk];

    // Streaming pointers (bwd walks T backwards)
    const float* xp = x + (long long)b * (Tn * In) + (dir ? (long long)(Tn - 1) * In : 0) + kk;
    const int dxp = dir ? -In : In;
    float* op = out + (long long)b * (Tn * 2 * Hn)
                    + (dir ? (long long)(Tn - 1) * 2 * Hn : 0) + dir * Hn + kk;
    const int dop = dir ? -(2 * Hn) : (2 * Hn);

    float h = 0.0f, c = 0.0f;
    float hcur = 0.0f;

    for (int t = 0; t < Tn; ++t) {
        const float xk = active ? __ldg(xp) : 0.0f;

        // LayerNorm stats over the 16-lane group (lanes 13-15 contribute 0)
        float s = xk, s2 = xk * xk;
#pragma unroll
        for (int m = 8; m >= 1; m >>= 1) {
            s  += __shfl_xor_sync(0xffffffffu, s,  m, 16);
            s2 += __shfl_xor_sync(0xffffffffu, s2, m, 16);
        }
        const float mu  = s * (1.0f / 13.0f);
        const float var = fmaf(-mu, mu, s2 * (1.0f / 13.0f));
        const float rs  = rsqf(var + 1e-5f);
        const float xn  = fmaf((xk - mu) * rs, lnw, lnb);

        U64 aif = bias_if, ago = bias_go;
#pragma unroll
        for (int j = 0; j < In; ++j) {
            const float xv = __shfl_sync(0xffffffffu, xn,   j, 16);
            const float hv = __shfl_sync(0xffffffffu, hcur, j, 16);
            const U64 xx = pk2(xv, xv);
            const U64 hh = pk2(hv, hv);
            aif = fma2(w_ih_if[j], xx, aif);
            ago = fma2(w_ih_go[j], xx, ago);
            aif = fma2(w_hh_if[j], hh, aif);
            ago = fma2(w_hh_go[j], hh, ago);
        }

        const float gi = sigm(lo2(aif));
        const float gf = sigm(hi2(aif));
        const float gg = tanhx(lo2(ago));
        const float go = sigm(hi2(ago));

        c = fmaf(gf, c, gi * gg);
        h = go * tanhx(c);
        hcur = h;

        if (active) *op = h;
        xp += dxp;
        op += dop;
    }

    if (active) {
        // h_n at OUT_ELEMS, c_n at OUT_ELEMS + HN_ELEMS; layout [dir][b][k]
        float* hn = out + OUT_ELEMS + (long long)dir * (Bn * Hn) + (long long)b * Hn + k;
        hn[0] = h;
        hn[HN_ELEMS] = c;
    }
}

extern "C" void kernel_launch(void* const* d_in, const int* in_sizes, int n_in,
                              void* d_out, int out_size)
{
    const float* x     = (const float*)d_in[0];
    const float* ln_w  = (const float*)d_in[1];
    const float* ln_b  = (const float*)d_in[2];
    const float* wih_f = (const float*)d_in[3];
    const float* whh_f = (const float*)d_in[4];
    const float* bih_f = (const float*)d_in[5];
    const float* bhh_f = (const float*)d_in[6];
    const float* wih_b = (const float*)d_in[7];
    const float* whh_b = (const float*)d_in[8];
    const float* bih_b = (const float*)d_in[9];
    const float* bhh_b = (const float*)d_in[10];
    float* out = (float*)d_out;

    // 2048 warps (one per batch row), 64-thread blocks -> 1024 blocks.
    // __launch_bounds__(64,7) caps regs at 146 -> 14 warps/SM -> single wave.
    bilstm_kernel<<<1024, 64>>>(x, ln_w, ln_b,
                                wih_f, whh_f, bih_f, bhh_f,
                                wih_b, whh_b, bih_b, bhh_b,
                                out);
}

// round 3
// speedup vs baseline: 1.0403x; 1.0403x over previous
#include <cuda_runtime.h>

typedef unsigned long long U64;

// ---------------- packed f32x2 helpers (Blackwell FFMA2, PTX-only) ----------------
__device__ __forceinline__ U64 pk2(float x, float y) {
    U64 r; asm("mov.b64 %0, {%1, %2};" : "=l"(r) : "f"(x), "f"(y)); return r;
}
__device__ __forceinline__ float lo2(U64 v) {
    float x; asm("{ .reg .f32 hi; mov.b64 {%0, hi}, %1; }" : "=f"(x) : "l"(v)); return x;
}
__device__ __forceinline__ float hi2(U64 v) {
    float y; asm("{ .reg .f32 lo; mov.b64 {lo, %0}, %1; }" : "=f"(y) : "l"(v)); return y;
}
__device__ __forceinline__ U64 fma2(U64 a, U64 b, U64 c) {
    U64 d; asm("fma.rn.f32x2 %0, %1, %2, %3;" : "=l"(d) : "l"(a), "l"(b), "l"(c)); return d;
}

// ---------------- fast transcendentals ----------------
__device__ __forceinline__ float ex2f(float x) { float r; asm("ex2.approx.f32 %0, %1;" : "=f"(r) : "f"(x)); return r; }
__device__ __forceinline__ float rcpf(float x) { float r; asm("rcp.approx.f32 %0, %1;" : "=f"(r) : "f"(x)); return r; }
__device__ __forceinline__ float rsqf(float x) { float r; asm("rsqrt.approx.f32 %0, %1;" : "=f"(r) : "f"(x)); return r; }

__device__ __forceinline__ float sigm(float v) {
    return rcpf(1.0f + ex2f(v * -1.4426950408889634f));
}
__device__ __forceinline__ float tanhx(float v) {
    return fmaf(-2.0f, rcpf(1.0f + ex2f(v * 2.8853900817779268f)), 1.0f);
}

static constexpr int Tn = 1000;
static constexpr int In = 13;
static constexpr int Hn = 13;
static constexpr int Bn = 2048;
static constexpr int TCHUNK = 20;                                    // Tn % TCHUNK == 0
static constexpr long long OUT_ELEMS = (long long)Bn * Tn * 2 * Hn;  // 53,248,000
static constexpr long long HN_ELEMS  = 2LL * Bn * Hn;

// Scratch: gate preactivations (i,f,g,o) per (b,t,dir,k).  852 MB.
__device__ float4 g_pre[(long long)Bn * Tn * 2 * Hn];

// =====================================================================
// Kernel A: fully parallel x-path.
// out g_pre[((b*Tn+t)*2+dir)*Hn+k] = W_ih[dir] rows {k,13+k,26+k,39+k} . LN(x[b,t]) + b_ih + b_hh
// One warp per (b, 20-t chunk). Lanes 0-15 fwd, 16-31 bwd; lane owns hidden k.
// W_ih packed by j-pairs so fma2 consumes (xn_j, xn_{j+1}) from LDS.64.
// =====================================================================
__global__ void __launch_bounds__(128, 5) xpre_kernel(
    const float* __restrict__ x,
    const float* __restrict__ ln_w, const float* __restrict__ ln_b,
    const float* __restrict__ wih_f, const float* __restrict__ bih_f, const float* __restrict__ bhh_f,
    const float* __restrict__ wih_b, const float* __restrict__ bih_b, const float* __restrict__ bhh_b)
{
    __shared__ __align__(16) float xnsm[4][2][16];   // [warp][buf][pad to 16]

    const int lane = threadIdx.x & 31;
    const int w    = threadIdx.x >> 5;
    const int dir  = lane >> 4;
    const int k    = lane & 15;
    const bool active = (k < Hn);
    const int kk   = active ? k : 0;

    const int b  = blockIdx.y * 4 + w;
    const int t0 = blockIdx.x * TCHUNK;

    const float* Wih = dir ? wih_b : wih_f;
    const float* Bih = dir ? bih_b : bih_f;
    const float* Bhh = dir ? bhh_b : bhh_f;

    U64 wp[4][7];
    float bias[4];
#pragma unroll
    for (int r = 0; r < 4; ++r) {
        const int row = r * Hn + kk;
        bias[r] = __ldg(&Bih[row]) + __ldg(&Bhh[row]);
#pragma unroll
        for (int jj = 0; jj < 7; ++jj) {
            const float wlo = __ldg(&Wih[row * In + 2 * jj]);
            const float whi = (2 * jj + 1 < In) ? __ldg(&Wih[row * In + 2 * jj + 1]) : 0.0f;
            wp[r][jj] = pk2(wlo, whi);
        }
    }
    const float lnwk = __ldg(&ln_w[kk]);
    const float lnbk = __ldg(&ln_b[kk]);

    // zero pad entries of both buffers (indices 13..15)
    if (dir == 0) { xnsm[w][0][k] = 0.0f; xnsm[w][1][k] = 0.0f; }
    __syncwarp();

    const float* xp = x + ((long long)b * Tn + t0) * In;
    float4* gp = g_pre + (((long long)b * Tn + t0) * 2 + dir) * Hn + kk;

    for (int tt = 0; tt < TCHUNK; ++tt) {
        const int buf = tt & 1;
        const float xk = active ? __ldg(xp + kk) : 0.0f;

        // LayerNorm stats over the 16-lane group (both halves compute identically)
        float s = xk, s2 = xk * xk;
#pragma unroll
        for (int m = 8; m >= 1; m >>= 1) {
            s  += __shfl_xor_sync(0xffffffffu, s,  m, 16);
            s2 += __shfl_xor_sync(0xffffffffu, s2, m, 16);
        }
        const float mu  = s * (1.0f / 13.0f);
        const float var = fmaf(-mu, mu, s2 * (1.0f / 13.0f));
        const float rs  = rsqf(var + 1e-5f);
        const float xn  = fmaf((xk - mu) * rs, lnwk, lnbk);

        if (dir == 0 && active) xnsm[w][buf][k] = xn;
        __syncwarp();

        U64 xpair[7];
#pragma unroll
        for (int jj = 0; jj < 7; ++jj)
            xpair[jj] = *(const U64*)&xnsm[w][buf][2 * jj];

        U64 a0 = pk2(bias[0], 0.0f), a1 = pk2(bias[1], 0.0f);
        U64 a2 = pk2(bias[2], 0.0f), a3 = pk2(bias[3], 0.0f);
#pragma unroll
        for (int jj = 0; jj < 7; ++jj) {
            a0 = fma2(wp[0][jj], xpair[jj], a0);
            a1 = fma2(wp[1][jj], xpair[jj], a1);
            a2 = fma2(wp[2][jj], xpair[jj], a2);
            a3 = fma2(wp[3][jj], xpair[jj], a3);
        }
        float4 g4;
        g4.x = lo2(a0) + hi2(a0);
        g4.y = lo2(a1) + hi2(a1);
        g4.z = lo2(a2) + hi2(a2);
        g4.w = lo2(a3) + hi2(a3);
        if (active) *gp = g4;

        gp += 2 * Hn;
        xp += In;
    }
}

// =====================================================================
// Kernel B: recurrence only. One warp per batch row; lanes 0-15 fwd,
// 16-31 bwd (walking t in reverse). Per step: prefetched LDG.128 of gate
// preacts, h exchanged via double-buffered smem (STS + syncwarp + 7 LDS.64),
// W_hh j-pair packed -> 28 fma2, activations, c/h update, STG.
// =====================================================================
__global__ void __launch_bounds__(64, 7) rec_kernel(
    const float* __restrict__ whh_f, const float* __restrict__ whh_b,
    float* __restrict__ out)
{
    __shared__ __align__(16) float hsm[2][2][2][16];  // [warp][buf][dir][pad 16]

    const int lane = threadIdx.x & 31;
    const int w    = threadIdx.x >> 5;
    const int dir  = lane >> 4;
    const int k    = lane & 15;
    const bool active = (k < Hn);
    const int kk   = active ? k : 0;
    const int b    = blockIdx.x * 2 + w;

    const float* Whh = dir ? whh_b : whh_f;

    U64 wp[4][7];
#pragma unroll
    for (int r = 0; r < 4; ++r) {
        const int row = r * Hn + kk;
#pragma unroll
        for (int jj = 0; jj < 7; ++jj) {
            const float wlo = __ldg(&Whh[row * Hn + 2 * jj]);
            const float whi = (2 * jj + 1 < Hn) ? __ldg(&Whh[row * Hn + 2 * jj + 1]) : 0.0f;
            wp[r][jj] = pk2(wlo, whi);
        }
    }

    // zero both buffers (covers pad indices too: k runs 0..15)
    hsm[w][0][dir][k] = 0.0f;
    hsm[w][1][dir][k] = 0.0f;
    __syncwarp();

    const float4* gp = g_pre + (((long long)b * Tn + (dir ? Tn - 1 : 0)) * 2 + dir) * Hn + kk;
    const int dgp = dir ? -(2 * Hn) : (2 * Hn);
    float* op = out + (long long)b * (Tn * 2 * Hn)
                    + (dir ? (long long)(Tn - 1) * 2 * Hn : 0) + dir * Hn + kk;
    const int dop = dir ? -(2 * Hn) : (2 * Hn);

    float c = 0.0f, h = 0.0f;
    float4 gnext = __ldg(gp);

    for (int t = 0; t < Tn; ++t) {
        const float4 g = gnext;
        if (t + 1 < Tn) gnext = __ldg(gp + dgp);   // prefetch: no serial dependence
        gp += dgp;

        const int cur = t & 1, nxt = cur ^ 1;

        U64 hp[7];
#pragma unroll
        for (int jj = 0; jj < 7; ++jj)
            hp[jj] = *(const U64*)&hsm[w][cur][dir][2 * jj];

        U64 a0 = pk2(g.x, 0.0f), a1 = pk2(g.y, 0.0f);
        U64 a2 = pk2(g.z, 0.0f), a3 = pk2(g.w, 0.0f);
#pragma unroll
        for (int jj = 0; jj < 7; ++jj) {
            a0 = fma2(wp[0][jj], hp[jj], a0);
            a1 = fma2(wp[1][jj], hp[jj], a1);
            a2 = fma2(wp[2][jj], hp[jj], a2);
            a3 = fma2(wp[3][jj], hp[jj], a3);
        }

        const float gi = sigm(lo2(a0) + hi2(a0));
        const float gf = sigm(lo2(a1) + hi2(a1));
        const float gg = tanhx(lo2(a2) + hi2(a2));
        const float go = sigm(lo2(a3) + hi2(a3));

        c = fmaf(gf, c, gi * gg);
        h = go * tanhx(c);

        if (active) { hsm[w][nxt][dir][k] = h; *op = h; }
        op += dop;
        __syncwarp();   // orders this step's h-writes before next step's reads
    }

    if (active) {
        float* hn = out + OUT_ELEMS + (long long)dir * (Bn * Hn) + (long long)b * Hn + k;
        hn[0] = h;
        hn[HN_ELEMS] = c;
    }
}

extern "C" void kernel_launch(void* const* d_in, const int* in_sizes, int n_in,
                              void* d_out, int out_size)
{
    const float* x     = (const float*)d_in[0];
    const float* ln_w  = (const float*)d_in[1];
    const float* ln_b  = (const float*)d_in[2];
    const float* wih_f = (const float*)d_in[3];
    const float* whh_f = (const float*)d_in[4];
    const float* bih_f = (const float*)d_in[5];
    const float* bhh_f = (const float*)d_in[6];
    const float* wih_b = (const float*)d_in[7];
    const float* whh_b = (const float*)d_in[8];
    const float* bih_b = (const float*)d_in[9];
    const float* bhh_b = (const float*)d_in[10];
    float* out = (float*)d_out;

    // Kernel A: (50 t-chunks) x (512 b-groups of 4 warps)
    dim3 gridA(Tn / TCHUNK, Bn / 4);
    xpre_kernel<<<gridA, 128>>>(x, ln_w, ln_b,
                                wih_f, bih_f, bhh_f,
                                wih_b, bih_b, bhh_b);

    // Kernel B: one warp per batch row, 2 warps/block
    rec_kernel<<<Bn / 2, 64>>>(whh_f, whh_b, out);
}

// round 4
// speedup vs baseline: 1.3157x; 1.2647x over previous
#include <cuda_runtime.h>

typedef unsigned long long U64;

// ---------------- packed f32x2 helpers (Blackwell FFMA2, PTX-only) ----------------
__device__ __forceinline__ U64 pk2(float x, float y) {
    U64 r; asm("mov.b64 %0, {%1, %2};" : "=l"(r) : "f"(x), "f"(y)); return r;
}
__device__ __forceinline__ float lo2(U64 v) {
    float x; asm("{ .reg .f32 hi; mov.b64 {%0, hi}, %1; }" : "=f"(x) : "l"(v)); return x;
}
__device__ __forceinline__ float hi2(U64 v) {
    float y; asm("{ .reg .f32 lo; mov.b64 {lo, %0}, %1; }" : "=f"(y) : "l"(v)); return y;
}
__device__ __forceinline__ U64 fma2(U64 a, U64 b, U64 c) {
    U64 d; asm("fma.rn.f32x2 %0, %1, %2, %3;" : "=l"(d) : "l"(a), "l"(b), "l"(c)); return d;
}
__device__ __forceinline__ U64 add2(U64 a, U64 b) {
    U64 d; asm("add.rn.f32x2 %0, %1, %2;" : "=l"(d) : "l"(a), "l"(b)); return d;
}

// ---------------- fast transcendentals ----------------
__device__ __forceinline__ float rsqf(float x) { float r; asm("rsqrt.approx.f32 %0, %1;" : "=f"(r) : "f"(x)); return r; }
__device__ __forceinline__ float tanh_ap(float x) { float r; asm("tanh.approx.f32 %0, %1;" : "=f"(r) : "f"(x)); return r; }
__device__ __forceinline__ float sigm_ap(float v) {
    return fmaf(tanh_ap(0.5f * v), 0.5f, 0.5f);
}

static constexpr int Tn = 1000;
static constexpr int In = 13;
static constexpr int Hn = 13;
static constexpr int Bn = 2048;
static constexpr long long OUT_ELEMS = (long long)Bn * Tn * 2 * Hn;  // 53,248,000
static constexpr long long HN_ELEMS  = 2LL * Bn * Hn;

// Scratch: gate preactivations (i,f,g,o) per (b,t,dir,k).  852 MB.
__device__ float4 g_pre[(long long)Bn * Tn * 2 * Hn];

// =====================================================================
// Kernel A: x-path, one THREAD per (b,t). LayerNorm folded into weights:
//   y = rs*(W'.x - mu*u) + v,  W' = W .* lnw (cols), u = row-sums of W',
//   v = W.lnb + b_ih + b_hh.  S,S2 computed locally per thread -> no shuffles.
// Weights broadcast from smem (uniform address across lanes, conflict-free).
// 104 rows handled as 52 f32x2 row-pairs; 26 independent accumulators/dir.
// =====================================================================
__global__ void __launch_bounds__(128, 3) xpre_kernel(
    const float* __restrict__ x,
    const float* __restrict__ ln_w, const float* __restrict__ ln_b,
    const float* __restrict__ wih_f, const float* __restrict__ bih_f, const float* __restrict__ bhh_f,
    const float* __restrict__ wih_b, const float* __restrict__ bih_b, const float* __restrict__ bhh_b)
{
    __shared__ __align__(8) float wsm[13][52][2];   // [j][rowpair][half]
    __shared__ __align__(8) float usm[52][2];
    __shared__ __align__(8) float vsm[52][2];

    const int tid = threadIdx.x;

    // Prologue: build folded-weight tables (104 rows over 104 threads)
    if (tid < 104) {
        const int dir = tid / 52;
        const int r   = tid % 52;
        const float* W  = dir ? wih_b : wih_f;
        const float* Bi = dir ? bih_b : bih_f;
        const float* Bh = dir ? bhh_b : bhh_f;
        float u = 0.0f;
        float v = __ldg(&Bi[r]) + __ldg(&Bh[r]);
#pragma unroll
        for (int j = 0; j < In; ++j) {
            const float wv = __ldg(&W[r * In + j]);
            const float lw = __ldg(&ln_w[j]);
            const float wp = wv * lw;
            wsm[j][tid >> 1][tid & 1] = wp;
            u += wp;
            v = fmaf(wv, __ldg(&ln_b[j]), v);
        }
        usm[tid >> 1][tid & 1] = u;
        vsm[tid >> 1][tid & 1] = v;
    }
    __syncthreads();

    const int b = blockIdx.y;
    const int t = blockIdx.x * 128 + tid;
    const bool act = (t < Tn);

    // Load this timestep's x row; local stats (no reduction needed)
    float xv[In];
    float S = 0.0f, S2 = 0.0f;
    const float* xp = x + ((long long)b * Tn + t) * In;
#pragma unroll
    for (int j = 0; j < In; ++j) {
        xv[j] = act ? __ldg(xp + j) : 0.0f;
        S += xv[j];
        S2 = fmaf(xv[j], xv[j], S2);
    }
    const float mu  = S * (1.0f / 13.0f);
    const float var = fmaf(-mu, mu, S2 * (1.0f / 13.0f));
    const float rs  = rsqf(var + 1e-5f);
    const U64 nmu2 = pk2(-mu, -mu);
    const U64 rs2  = pk2(rs, rs);

    float4* gp = g_pre + ((long long)b * Tn + t) * 2 * Hn;

#pragma unroll
    for (int d = 0; d < 2; ++d) {
        U64 acc[26];
#pragma unroll
        for (int p = 0; p < 26; ++p) acc[p] = 0ULL;

        for (int j = 0; j < In; ++j) {             // rolled: keeps I-cache small
            const U64 xj2 = pk2(xv[j], xv[j]);
#pragma unroll
            for (int p = 0; p < 26; ++p)
                acc[p] = fma2(*(const U64*)&wsm[j][d * 26 + p][0], xj2, acc[p]);
        }

        float row[52];
#pragma unroll
        for (int p = 0; p < 26; ++p) {
            const U64 tmp = fma2(*(const U64*)&usm[d * 26 + p][0], nmu2, acc[p]);
            const U64 y   = fma2(tmp, rs2, *(const U64*)&vsm[d * 26 + p][0]);
            row[2 * p]     = lo2(y);
            row[2 * p + 1] = hi2(y);
        }
        if (act) {
#pragma unroll
            for (int k = 0; k < Hn; ++k)
                gp[d * Hn + k] = make_float4(row[k], row[Hn + k], row[2 * Hn + k], row[3 * Hn + k]);
        }
    }
}

// =====================================================================
// Kernel B: recurrence. One warp per batch row; lanes 0-15 fwd, 16-31 bwd.
// h stored DUPLICATED (h,h) in smem so row-pairs (i,f)/(g,o) accumulate
// directly (no horizontal adds). Dual accumulators halve the fma2 chain.
// tanh.approx for all activations (5 MUFU/step).
// =====================================================================
__global__ void __launch_bounds__(64, 7) rec_kernel(
    const float* __restrict__ whh_f, const float* __restrict__ whh_b,
    float* __restrict__ out)
{
    // [warp][buf][dir][pad to 14]  (dir stride 112B -> cross-dir bank-free)
    __shared__ __align__(8) float2 hsm[2][2][2][14];

    const int lane = threadIdx.x & 31;
    const int w    = threadIdx.x >> 5;
    const int dir  = lane >> 4;
    const int k    = lane & 15;
    const bool active = (k < Hn);
    const int kk   = active ? k : 0;
    const int b    = blockIdx.x * 2 + w;

    const float* Whh = dir ? whh_b : whh_f;

    // Row pairs: wif[j] = (W[i_k][j], W[f_k][j]),  wgo[j] = (W[g_k][j], W[o_k][j])
    U64 wif[In], wgo[In];
#pragma unroll
    for (int j = 0; j < In; ++j) {
        wif[j] = pk2(__ldg(&Whh[kk * Hn + j]),            __ldg(&Whh[(Hn + kk) * Hn + j]));
        wgo[j] = pk2(__ldg(&Whh[(2 * Hn + kk) * Hn + j]), __ldg(&Whh[(3 * Hn + kk) * Hn + j]));
    }

    if (active) {
        hsm[w][0][dir][k] = make_float2(0.0f, 0.0f);
        hsm[w][1][dir][k] = make_float2(0.0f, 0.0f);
    }
    __syncwarp();

    const float4* gp = g_pre + (((long long)b * Tn + (dir ? Tn - 1 : 0)) * 2 + dir) * Hn + kk;
    const int dgp = dir ? -(2 * Hn) : (2 * Hn);
    float* op = out + (long long)b * (Tn * 2 * Hn)
                    + (dir ? (long long)(Tn - 1) * 2 * Hn : 0) + dir * Hn + kk;
    const int dop = dir ? -(2 * Hn) : (2 * Hn);

    float c = 0.0f, h = 0.0f;
    float4 gnext = __ldg(gp);

    for (int t = 0; t < Tn; ++t) {
        const float4 g = gnext;
        if (t + 1 < Tn) gnext = __ldg(gp + dgp);   // prefetch: no serial dependence
        gp += dgp;

        const int cur = t & 1, nxt = cur ^ 1;

        // Dual accumulators: 7-deep chains instead of 13
        U64 aif0 = pk2(g.x, g.y), aif1 = 0ULL;
        U64 ago0 = pk2(g.z, g.w), ago1 = 0ULL;
#pragma unroll
        for (int j = 0; j < 12; j += 2) {
            const U64 h0 = *(const U64*)&hsm[w][cur][dir][j];
            const U64 h1 = *(const U64*)&hsm[w][cur][dir][j + 1];
            aif0 = fma2(wif[j],     h0, aif0);
            ago0 = fma2(wgo[j],     h0, ago0);
            aif1 = fma2(wif[j + 1], h1, aif1);
            ago1 = fma2(wgo[j + 1], h1, ago1);
        }
        {
            const U64 h12 = *(const U64*)&hsm[w][cur][dir][12];
            aif0 = fma2(wif[12], h12, aif0);
            ago0 = fma2(wgo[12], h12, ago0);
        }
        const U64 aif = add2(aif0, aif1);
        const U64 ago = add2(ago0, ago1);

        const float gi = sigm_ap(lo2(aif));
        const float gf = sigm_ap(hi2(aif));
        const float gg = tanh_ap(lo2(ago));
        const float go = sigm_ap(hi2(ago));

        c = fmaf(gf, c, gi * gg);
        h = go * tanh_ap(c);

        if (active) { hsm[w][nxt][dir][k] = make_float2(h, h); *op = h; }
        op += dop;
        __syncwarp();   // orders this step's h-writes before next step's reads
    }

    if (active) {
        float* hn = out + OUT_ELEMS + (long long)dir * (Bn * Hn) + (long long)b * Hn + k;
        hn[0] = h;
        hn[HN_ELEMS] = c;
    }
}

extern "C" void kernel_launch(void* const* d_in, const int* in_sizes, int n_in,
                              void* d_out, int out_size)
{
    const float* x     = (const float*)d_in[0];
    const float* ln_w  = (const float*)d_in[1];
    const float* ln_b  = (const float*)d_in[2];
    const float* wih_f = (const float*)d_in[3];
    const float* whh_f = (const float*)d_in[4];
    const float* bih_f = (const float*)d_in[5];
    const float* bhh_f = (const float*)d_in[6];
    const float* wih_b = (const float*)d_in[7];
    const float* whh_b = (const float*)d_in[8];
    const float* bih_b = (const float*)d_in[9];
    const float* bhh_b = (const float*)d_in[10];
    float* out = (float*)d_out;

    // Kernel A: thread per (b,t).  grid = (t-chunks of 128, B)
    dim3 gridA((Tn + 127) / 128, Bn);
    xpre_kernel<<<gridA, 128>>>(x, ln_w, ln_b,
                                wih_f, bih_f, bhh_f,
                                wih_b, bih_b, bhh_b);

    // Kernel B: one warp per batch row, 2 warps/block
    rec_kernel<<<Bn / 2, 64>>>(whh_f, whh_b, out);
}

// round 5
// speedup vs baseline: 1.6438x; 1.2494x over previous
#include <cuda_runtime.h>

typedef unsigned long long U64;

// ---------------- packed f32x2 helpers (Blackwell FFMA2, PTX-only) ----------------
__device__ __forceinline__ U64 pk2(float x, float y) {
    U64 r; asm("mov.b64 %0, {%1, %2};" : "=l"(r) : "f"(x), "f"(y)); return r;
}
__device__ __forceinline__ float lo2(U64 v) {
    float x; asm("{ .reg .f32 hi; mov.b64 {%0, hi}, %1; }" : "=f"(x) : "l"(v)); return x;
}
__device__ __forceinline__ float hi2(U64 v) {
    float y; asm("{ .reg .f32 lo; mov.b64 {lo, %0}, %1; }" : "=f"(y) : "l"(v)); return y;
}
__device__ __forceinline__ U64 fma2(U64 a, U64 b, U64 c) {
    U64 d; asm("fma.rn.f32x2 %0, %1, %2, %3;" : "=l"(d) : "l"(a), "l"(b), "l"(c)); return d;
}
__device__ __forceinline__ U64 add2(U64 a, U64 b) {
    U64 d; asm("add.rn.f32x2 %0, %1, %2;" : "=l"(d) : "l"(a), "l"(b)); return d;
}

// ---------------- fast transcendentals ----------------
__device__ __forceinline__ float rsqf(float x) { float r; asm("rsqrt.approx.f32 %0, %1;" : "=f"(r) : "f"(x)); return r; }
__device__ __forceinline__ float tanh_ap(float x) { float r; asm("tanh.approx.f32 %0, %1;" : "=f"(r) : "f"(x)); return r; }
__device__ __forceinline__ float sigm_ap(float v) {
    return fmaf(tanh_ap(0.5f * v), 0.5f, 0.5f);
}

static constexpr int Tn = 1000;
static constexpr int In = 13;
static constexpr int Hn = 13;
static constexpr int Bn = 2048;
static constexpr long long OUT_ELEMS = (long long)Bn * Tn * 2 * Hn;  // 53,248,000
static constexpr long long HN_ELEMS  = 2LL * Bn * Hn;

// Scratch: gate preactivation float4 (i,f,g,o) laid out [dir][b][t][k].  852 MB.
__device__ float4 g_pre[2LL * Bn * Tn * Hn];

// =====================================================================
// Kernel A: x-path, one THREAD per (b,t). LayerNorm folded into weights:
//   y = rs*(W'.x - mu*u) + v,  W' = W .* lnw (cols), u = row-sums of W',
//   v = W.lnb + b_ih + b_hh.  S,S2 computed locally -> no shuffles.
// Results staged per-dir in smem (stride-13 float4 rows: STS.128
// conflict-free), then block-copied out with perfect linear coalescing.
// =====================================================================
__global__ void __launch_bounds__(128, 3) xpre_kernel(
    const float* __restrict__ x,
    const float* __restrict__ ln_w, const float* __restrict__ ln_b,
    const float* __restrict__ wih_f, const float* __restrict__ bih_f, const float* __restrict__ bhh_f,
    const float* __restrict__ wih_b, const float* __restrict__ bih_b, const float* __restrict__ bhh_b)
{
    __shared__ __align__(16) float4 ssm[128 * 13];     // 26,624 B staging
    __shared__ __align__(8)  float wsm[13][52][2];     // folded weights, both dirs
    __shared__ __align__(8)  float usm[52][2];
    __shared__ __align__(8)  float vsm[52][2];

    const int tid = threadIdx.x;

    // Prologue: build folded-weight tables (104 rows over 104 threads)
    if (tid < 104) {
        const int dir = tid / 52;
        const int r   = tid % 52;
        const float* W  = dir ? wih_b : wih_f;
        const float* Bi = dir ? bih_b : bih_f;
        const float* Bh = dir ? bhh_b : bhh_f;
        float u = 0.0f;
        float v = __ldg(&Bi[r]) + __ldg(&Bh[r]);
#pragma unroll
        for (int j = 0; j < In; ++j) {
            const float wv = __ldg(&W[r * In + j]);
            const float wp = wv * __ldg(&ln_w[j]);
            wsm[j][tid >> 1][tid & 1] = wp;
            u += wp;
            v = fmaf(wv, __ldg(&ln_b[j]), v);
        }
        usm[tid >> 1][tid & 1] = u;
        vsm[tid >> 1][tid & 1] = v;
    }
    __syncthreads();

    const int b  = blockIdx.y;
    const int t0 = blockIdx.x * 128;
    const int t  = t0 + tid;
    const bool act = (t < Tn);
    const int nvalid = (Tn - t0 < 128) ? (Tn - t0) : 128;

    // Load x row; local LN stats
    float xv[In];
    float S = 0.0f, S2 = 0.0f;
    const float* xp = x + ((long long)b * Tn + t) * In;
#pragma unroll
    for (int j = 0; j < In; ++j) {
        xv[j] = act ? __ldg(xp + j) : 0.0f;
        S += xv[j];
        S2 = fmaf(xv[j], xv[j], S2);
    }
    const float mu  = S * (1.0f / 13.0f);
    const float var = fmaf(-mu, mu, S2 * (1.0f / 13.0f));
    const float rs  = rsqf(var + 1e-5f);
    const U64 nmu2 = pk2(-mu, -mu);
    const U64 rs2  = pk2(rs, rs);

#pragma unroll
    for (int d = 0; d < 2; ++d) {
        U64 acc[26];
#pragma unroll
        for (int p = 0; p < 26; ++p) acc[p] = 0ULL;

        for (int j = 0; j < In; ++j) {             // rolled: small I-footprint
            const U64 xj2 = pk2(xv[j], xv[j]);
#pragma unroll
            for (int p = 0; p < 26; ++p)
                acc[p] = fma2(*(const U64*)&wsm[j][d * 26 + p][0], xj2, acc[p]);
        }

        float row[52];
#pragma unroll
        for (int p = 0; p < 26; ++p) {
            const U64 tmp = fma2(*(const U64*)&usm[d * 26 + p][0], nmu2, acc[p]);
            const U64 y   = fma2(tmp, rs2, *(const U64*)&vsm[d * 26 + p][0]);
            row[2 * p]     = lo2(y);
            row[2 * p + 1] = hi2(y);
        }

        // Stage this dir's 13 float4 (stride-13 rows: STS.128 conflict-free)
#pragma unroll
        for (int k = 0; k < Hn; ++k)
            ssm[tid * 13 + k] = make_float4(row[k], row[Hn + k], row[2 * Hn + k], row[3 * Hn + k]);
        __syncthreads();

        // Linear coalesced copy-out: smem index == dst index
        float4* dst = g_pre + ((long long)d * Bn * Tn + (long long)b * Tn + t0) * Hn;
        const int n = nvalid * 13;
        for (int i = tid; i < n; i += 128)
            dst[i] = ssm[i];
        __syncthreads();   // before ssm reuse by d=1
    }
}

// =====================================================================
// Kernel B: recurrence. One warp per batch row; lanes 0-15 fwd, 16-31 bwd.
// 4-deep register prefetch pipeline on gate preacts (MLP=4 vs DRAM
// latency). h stored DUPLICATED (h,h) in smem; dual accumulators;
// tanh.approx activations.
// =====================================================================
__global__ void __launch_bounds__(64, 7) rec_kernel(
    const float* __restrict__ whh_f, const float* __restrict__ whh_b,
    float* __restrict__ out)
{
    __shared__ __align__(8) float2 hsm[2][2][2][14];  // [warp][buf][dir][pad 14]

    const int lane = threadIdx.x & 31;
    const int w    = threadIdx.x >> 5;
    const int dir  = lane >> 4;
    const int k    = lane & 15;
    const bool active = (k < Hn);
    const int kk   = active ? k : 0;
    const int b    = blockIdx.x * 2 + w;

    const float* Whh = dir ? whh_b : whh_f;

    U64 wif[In], wgo[In];
#pragma unroll
    for (int j = 0; j < In; ++j) {
        wif[j] = pk2(__ldg(&Whh[kk * Hn + j]),            __ldg(&Whh[(Hn + kk) * Hn + j]));
        wgo[j] = pk2(__ldg(&Whh[(2 * Hn + kk) * Hn + j]), __ldg(&Whh[(3 * Hn + kk) * Hn + j]));
    }

    if (active) {
        hsm[w][0][dir][k] = make_float2(0.0f, 0.0f);
        hsm[w][1][dir][k] = make_float2(0.0f, 0.0f);
    }
    __syncwarp();

    // g_pre layout [dir][b][t][k]
    const float4* gbase = g_pre + ((long long)dir * Bn * Tn + (long long)b * Tn
                                   + (dir ? Tn - 1 : 0)) * Hn + kk;
    const int dgp = dir ? -Hn : Hn;
    const float4* gp = gbase;

    float* op = out + (long long)b * (Tn * 2 * Hn)
                    + (dir ? (long long)(Tn - 1) * 2 * Hn : 0) + dir * Hn + kk;
    const int dop = dir ? -(2 * Hn) : (2 * Hn);

    float c = 0.0f, h = 0.0f;

    // Prefetch pipeline: gb[i] holds g for step t0+i
    float4 gb[4];
#pragma unroll
    for (int i = 0; i < 4; ++i) { gb[i] = __ldg(gp); gp += dgp; }

#pragma unroll 4
    for (int t = 0; t < Tn; ++t) {
        const float4 g = gb[t & 3];
        if (t + 4 < Tn) { gb[t & 3] = __ldg(gp); gp += dgp; }

        const int cur = t & 1, nxt = cur ^ 1;

        U64 aif0 = pk2(g.x, g.y), aif1 = 0ULL;
        U64 ago0 = pk2(g.z, g.w), ago1 = 0ULL;
#pragma unroll
        for (int j = 0; j < 12; j += 2) {
            const U64 h0 = *(const U64*)&hsm[w][cur][dir][j];
            const U64 h1 = *(const U64*)&hsm[w][cur][dir][j + 1];
            aif0 = fma2(wif[j],     h0, aif0);
            ago0 = fma2(wgo[j],     h0, ago0);
            aif1 = fma2(wif[j + 1], h1, aif1);
            ago1 = fma2(wgo[j + 1], h1, ago1);
        }
        {
            const U64 h12 = *(const U64*)&hsm[w][cur][dir][12];
            aif0 = fma2(wif[12], h12, aif0);
            ago0 = fma2(wgo[12], h12, ago0);
        }
        const U64 aif = add2(aif0, aif1);
        const U64 ago = add2(ago0, ago1);

        const float gi = sigm_ap(lo2(aif));
        const float gf = sigm_ap(hi2(aif));
        const float gg = tanh_ap(lo2(ago));
        const float go = sigm_ap(hi2(ago));

        c = fmaf(gf, c, gi * gg);
        h = go * tanh_ap(c);

        if (active) { hsm[w][nxt][dir][k] = make_float2(h, h); *op = h; }
        op += dop;
        __syncwarp();
    }

    if (active) {
        float* hn = out + OUT_ELEMS + (long long)dir * (Bn * Hn) + (long long)b * Hn + k;
        hn[0] = h;
        hn[HN_ELEMS] = c;
    }
}

extern "C" void kernel_launch(void* const* d_in, const int* in_sizes, int n_in,
                              void* d_out, int out_size)
{
    const float* x     = (const float*)d_in[0];
    const float* ln_w  = (const float*)d_in[1];
    const float* ln_b  = (const float*)d_in[2];
    const float* wih_f = (const float*)d_in[3];
    const float* whh_f = (const float*)d_in[4];
    const float* bih_f = (const float*)d_in[5];
    const float* bhh_f = (const float*)d_in[6];
    const float* wih_b = (const float*)d_in[7];
    const float* whh_b = (const float*)d_in[8];
    const float* bih_b = (const float*)d_in[9];
    const float* bhh_b = (const float*)d_in[10];
    float* out = (float*)d_out;

    // Kernel A: thread per (b,t).  grid = (8 t-chunks, 2048 b)
    dim3 gridA((Tn + 127) / 128, Bn);
    xpre_kernel<<<gridA, 128>>>(x, ln_w, ln_b,
                                wih_f, bih_f, bhh_f,
                                wih_b, bih_b, bhh_b);

    // Kernel B: one warp per batch row, 2 warps/block
    rec_kernel<<<Bn / 2, 64>>>(whh_f, whh_b, out);
}